// round 1
// baseline (speedup 1.0000x reference)
#include <cuda_runtime.h>
#include <cstdint>
#include <cstddef>

typedef unsigned long long ULL;

#define CN   8192
#define CF   64
#define COUT 64
#define BM   64
#define BK   32

// ---- packed f32x2 helpers (sm_100+ PTX) ----
__device__ __forceinline__ ULL fma2(ULL a, ULL b, ULL c) {
    ULL d;
    asm("fma.rn.f32x2 %0, %1, %2, %3;" : "=l"(d) : "l"(a), "l"(b), "l"(c));
    return d;
}
__device__ __forceinline__ ULL pack2(float x, float y) {
    ULL u;
    asm("mov.b64 %0, {%1, %2};" : "=l"(u) : "f"(x), "f"(y));
    return u;
}
__device__ __forceinline__ float2 unpack2(ULL u) {
    float2 f;
    asm("mov.b64 {%0, %1}, %2;" : "=f"(f.x), "=f"(f.y) : "l"(u));
    return f;
}

// dynamic smem layout (bytes):
//   [0,      33792)  sAd  : float2[2][64*33]   adj tile, duplicated pairs, 2 buffers
//   [33792,  51200)  sF   : float [2][32*68]   feature tile, 2 buffers
//   epilogue aliases the [0, 33792) region:
//       sNT at 0      : float[64*66]  (neigh transposed, [c][row])
//       sFT at 16896  : float[64*66]  (features block transposed, [c][row])
//   [51200,  83968)  sWT  : float[128*64]      W transposed [c][o]
//   [83968,  84224)  sDeg : float[64]          1/(deg+1) per row
#define SMEM_BYTES 84224

__global__ __launch_bounds__(256, 1)
void sage_fused_kernel(const float* __restrict__ adj,
                       const float* __restrict__ feat,
                       const float* __restrict__ W,
                       float* __restrict__ out)
{
    extern __shared__ char smem[];
    float2* sAd  = reinterpret_cast<float2*>(smem);                 // pairs
    float*  sF   = reinterpret_cast<float*>(smem + 33792);
    float*  sNT  = reinterpret_cast<float*>(smem);                  // epilogue alias
    float*  sFT  = reinterpret_cast<float*>(smem + 16896);          // epilogue alias
    float*  sWT  = reinterpret_cast<float*>(smem + 51200);
    float*  sDeg = reinterpret_cast<float*>(smem + 83968);

    const int tid  = threadIdx.x;
    const int row0 = blockIdx.x * BM;

    // ---- stage W^T into smem once: sWT[c*64 + o] = W[o*128 + c] ----
    #pragma unroll
    for (int i = tid; i < COUT * 2 * CF; i += 256) {
        int o = i >> 7;           // 0..63
        int c = i & 127;          // 0..127
        sWT[c * 64 + o] = W[i];
    }

    // ---- load/store mappings ----
    const int lrow = tid >> 2;        // adj tile: row in tile (0..63)
    const int lq   = tid & 3;         // adj tile: 8-col chunk   (0..3)
    const int lk   = tid >> 3;        // f tile: k row (0..31)
    const int lc   = (tid & 7) * 8;   // f tile: col chunk start

    // compute mapping
    const int ty = tid >> 4;          // 0..15 -> rows ty*4..+3
    const int tx = tid & 15;          // 0..15 -> cols tx*4..+3 (2 pairs)

    float rA[8], rF[8];
    float dv = 0.0f;                  // deg partial for row (tid>>2)
    ULL acc[4][2];
    #pragma unroll
    for (int i = 0; i < 4; ++i) { acc[i][0] = 0ull; acc[i][1] = 0ull; }

    const size_t adjRowBase = (size_t)(row0 + lrow) * CN + (size_t)lq * 8;

    auto LOADT = [&](int t) {
        const int k0 = t * BK;
        const float4* pa = reinterpret_cast<const float4*>(adj + adjRowBase + k0);
        float4 a0 = __ldcs(pa);
        float4 a1 = __ldcs(pa + 1);
        rA[0] = a0.x; rA[1] = a0.y; rA[2] = a0.z; rA[3] = a0.w;
        rA[4] = a1.x; rA[5] = a1.y; rA[6] = a1.z; rA[7] = a1.w;
        const float4* pf = reinterpret_cast<const float4*>(feat + (size_t)(k0 + lk) * CF + lc);
        float4 f0 = __ldg(pf);
        float4 f1 = __ldg(pf + 1);
        rF[0] = f0.x; rF[1] = f0.y; rF[2] = f0.z; rF[3] = f0.w;
        rF[4] = f1.x; rF[5] = f1.y; rF[6] = f1.z; rF[7] = f1.w;
    };

    auto STORET = [&](int buf) {
        float2* sa = sAd + buf * 2112 + lrow * 33 + lq * 8;
        #pragma unroll
        for (int i = 0; i < 8; ++i) sa[i] = make_float2(rA[i], rA[i]);
        dv += ((rA[0] + rA[1]) + (rA[2] + rA[3])) + ((rA[4] + rA[5]) + (rA[6] + rA[7]));
        float* sf = sF + buf * 2176 + lk * 68 + lc;
        #pragma unroll
        for (int i = 0; i < 8; ++i) sf[i] = rF[i];
    };

    auto COMPUTET = [&](int buf) {
        const float2* aB = sAd + buf * 2112 + (ty * 4) * 33;
        const float*  bB = sF + buf * 2176 + tx * 4;
        #pragma unroll
        for (int kk = 0; kk < BK; ++kk) {
            ULL a0 = *reinterpret_cast<const ULL*>(aB + kk);
            ULL a1 = *reinterpret_cast<const ULL*>(aB + 33 + kk);
            ULL a2 = *reinterpret_cast<const ULL*>(aB + 66 + kk);
            ULL a3 = *reinterpret_cast<const ULL*>(aB + 99 + kk);
            ulonglong2 b = *reinterpret_cast<const ulonglong2*>(bB + (size_t)kk * 68);
            acc[0][0] = fma2(a0, b.x, acc[0][0]);
            acc[0][1] = fma2(a0, b.y, acc[0][1]);
            acc[1][0] = fma2(a1, b.x, acc[1][0]);
            acc[1][1] = fma2(a1, b.y, acc[1][1]);
            acc[2][0] = fma2(a2, b.x, acc[2][0]);
            acc[2][1] = fma2(a2, b.y, acc[2][1]);
            acc[3][0] = fma2(a3, b.x, acc[3][0]);
            acc[3][1] = fma2(a3, b.y, acc[3][1]);
        }
    };

    // ---- main loop: register-prefetch double buffering, 1 barrier / tile ----
    const int T = CN / BK;   // 256
    LOADT(0);
    STORET(0);
    __syncthreads();

    for (int t = 0; t < T; ++t) {
        const int cur = t & 1;
        const bool hasNext = (t + 1) < T;
        if (hasNext) LOADT(t + 1);
        COMPUTET(cur);
        if (hasNext) {
            STORET(cur ^ 1);
            __syncthreads();
        }
    }

    // ---- deg reduction: 4 consecutive lanes own one row ----
    dv += __shfl_xor_sync(0xffffffffu, dv, 1);
    dv += __shfl_xor_sync(0xffffffffu, dv, 2);
    if ((tid & 3) == 0) sDeg[tid >> 2] = 1.0f / (dv + 1.0f);
    __syncthreads();   // also ensures all COMPUTET done before smem is re-purposed

    // ---- write transposed neigh = acc * inv(deg) into sNT[c*66 + row] ----
    {
        float inv[4];
        #pragma unroll
        for (int i = 0; i < 4; ++i) inv[i] = sDeg[ty * 4 + i];
        #pragma unroll
        for (int i = 0; i < 4; ++i) {
            const int row = ty * 4 + i;
            #pragma unroll
            for (int j2 = 0; j2 < 2; ++j2) {
                float2 v = unpack2(acc[i][j2]);
                const int c0 = tx * 4 + j2 * 2;
                sNT[c0 * 66 + row]       = v.x * inv[i];
                sNT[(c0 + 1) * 66 + row] = v.y * inv[i];
            }
        }
    }

    // ---- stage features block transposed: sFT[c*66 + row] ----
    {
        const int fr = tid >> 2;          // row 0..63
        const int fq = tid & 3;           // 16-col chunk
        const float* frow = feat + (size_t)(row0 + fr) * CF + fq * 16;
        #pragma unroll
        for (int u = 0; u < 4; ++u) {
            float4 q = __ldg(reinterpret_cast<const float4*>(frow + u * 4));
            const int cb = fq * 16 + u * 4;
            sFT[(cb + 0) * 66 + fr] = q.x;
            sFT[(cb + 1) * 66 + fr] = q.y;
            sFT[(cb + 2) * 66 + fr] = q.z;
            sFT[(cb + 3) * 66 + fr] = q.w;
        }
    }
    __syncthreads();

    // ---- epilogue: out[r][o] = sum_c f[r][c]*W[o][c] + neigh[r][c]*W[o][64+c] ----
    {
        const int o  = tid & 63;          // output column (lane-contiguous)
        const int rg = tid >> 6;          // 0..3 -> rows rg*16..+15 (8 pairs)
        ULL acc_e[8];
        #pragma unroll
        for (int p = 0; p < 8; ++p) acc_e[p] = 0ull;

        #pragma unroll 4
        for (int c = 0; c < CF; ++c) {
            const float wa = sWT[c * 64 + o];
            const float wb = sWT[(c + 64) * 64 + o];
            const ULL wa2 = pack2(wa, wa);
            const ULL wb2 = pack2(wb, wb);
            const float* fc = sFT + c * 66 + rg * 16;
            const float* nc = sNT + c * 66 + rg * 16;
            #pragma unroll
            for (int p = 0; p < 8; ++p) {
                ULL f2 = *reinterpret_cast<const ULL*>(fc + 2 * p);
                ULL n2 = *reinterpret_cast<const ULL*>(nc + 2 * p);
                acc_e[p] = fma2(f2, wa2, acc_e[p]);
                acc_e[p] = fma2(n2, wb2, acc_e[p]);
            }
        }

        #pragma unroll
        for (int p = 0; p < 8; ++p) {
            float2 v = unpack2(acc_e[p]);
            const int r = row0 + rg * 16 + 2 * p;
            out[(size_t)r * COUT + o]       = v.x;
            out[(size_t)(r + 1) * COUT + o] = v.y;
        }
    }
}

extern "C" void kernel_launch(void* const* d_in, const int* in_sizes, int n_in,
                              void* d_out, int out_size)
{
    const float* adj  = nullptr;
    const float* feat = nullptr;
    const float* W    = nullptr;
    for (int i = 0; i < n_in; ++i) {
        const int s = in_sizes[i];
        if (s == CN * CN)            adj  = (const float*)d_in[i];
        else if (s == CN * CF)       feat = (const float*)d_in[i];
        else if (s == COUT * 2 * CF) W    = (const float*)d_in[i];
    }
    cudaFuncSetAttribute(sage_fused_kernel,
                         cudaFuncAttributeMaxDynamicSharedMemorySize, SMEM_BYTES);
    sage_fused_kernel<<<CN / BM, 256, SMEM_BYTES>>>(adj, feat, W, (float*)d_out);
}

// round 5
// speedup vs baseline: 1.4178x; 1.4178x over previous
#include <cuda_runtime.h>
#include <cuda_bf16.h>
#include <cstdint>
#include <cstddef>

typedef unsigned long long ULL;

#define CN   8192
#define CF   64
#define COUT 64
#define BM   64
#define BK   32
#define ITERS 256          // CN / BK

#define A_STRIDE 80        // bytes per smem A row (32 bf16 + pad) -> conflict-free LDSM
#define B_STRIDE 80
#define A_BYTES  (BM * A_STRIDE)      // 5120
#define B_ROWS   96                   // 72 used (64 feat + 1 ones + 7 pad), 96 for uniform loads
#define B_BYTES  (B_ROWS * B_STRIDE)  // 7680
#define STAGE    (A_BYTES + B_BYTES)  // 12800, x2 stages = 25600

// epilogue smem (sNT aliases the stage region, written after mainloop)
#define OFF_SNT 0
#define OFF_SFT 25600
#define OFF_SWT 42496
#define SMEM_BYTES 75264
#define PITCH 66

// blocked bf16 feat^T: [t][n(96)][kk(32)]  (k = t*32+kk); n=64 row is ones
__device__ uint4 g_featB[ITERS * 384];   // 384 uint4 = 6144B per block

// ---------------- helpers ----------------
__device__ __forceinline__ uint32_t smem_u32(const void* p) {
    uint32_t a;
    asm("{ .reg .u64 t; cvta.to.shared.u64 t, %1; cvt.u32.u64 %0, t; }" : "=r"(a) : "l"(p));
    return a;
}
__device__ __forceinline__ ULL fma2(ULL a, ULL b, ULL c) {
    ULL d; asm("fma.rn.f32x2 %0, %1, %2, %3;" : "=l"(d) : "l"(a), "l"(b), "l"(c)); return d;
}
__device__ __forceinline__ ULL pack2(float x, float y) {
    ULL u; asm("mov.b64 %0, {%1, %2};" : "=l"(u) : "f"(x), "f"(y)); return u;
}
__device__ __forceinline__ float2 unpack2(ULL u) {
    float2 f; asm("mov.b64 {%0, %1}, %2;" : "=f"(f.x), "=f"(f.y) : "l"(u)); return f;
}
// pack {lo,hi} floats into bf16x2 (lo in bits[15:0])
__device__ __forceinline__ uint32_t cvt2(float lo, float hi) {
    uint32_t r; asm("cvt.rn.bf16x2.f32 %0, %1, %2;" : "=r"(r) : "f"(hi), "f"(lo)); return r;
}

#define LDSM4(r0, r1, r2, r3, addr) \
    asm volatile("ldmatrix.sync.aligned.m8n8.x4.shared.b16 {%0,%1,%2,%3}, [%4];" \
                 : "=r"(r0), "=r"(r1), "=r"(r2), "=r"(r3) : "r"(addr))
#define LDSM2(r0, r1, addr) \
    asm volatile("ldmatrix.sync.aligned.m8n8.x2.shared.b16 {%0,%1}, [%2];" \
                 : "=r"(r0), "=r"(r1) : "r"(addr))

__device__ __forceinline__ void mma16816(float* d, uint32_t a0, uint32_t a1, uint32_t a2,
                                         uint32_t a3, uint32_t b0, uint32_t b1) {
    asm volatile("mma.sync.aligned.m16n8k16.row.col.f32.bf16.bf16.f32 "
                 "{%0,%1,%2,%3},{%4,%5,%6,%7},{%8,%9},{%0,%1,%2,%3};"
                 : "+f"(d[0]), "+f"(d[1]), "+f"(d[2]), "+f"(d[3])
                 : "r"(a0), "r"(a1), "r"(a2), "r"(a3), "r"(b0), "r"(b1));
}

// ---------------- prep: blocked bf16 feat^T with ones row ----------------
__global__ void prep_featB(const float* __restrict__ feat) {
    int idx = blockIdx.x * 256 + threadIdx.x;        // < 256*3072
    int t   = idx / 3072;
    int rem = idx - t * 3072;
    int n   = rem >> 5;
    int kk  = rem & 31;
    int k   = t * BK + kk;
    float v = (n < CF) ? feat[k * CF + n] : (n == CF ? 1.0f : 0.0f);
    reinterpret_cast<__nv_bfloat16*>(g_featB)[idx] = __float2bfloat16_rn(v);
}

// ---------------- main fused kernel ----------------
__global__ __launch_bounds__(128)
void sage_mma_kernel(const float* __restrict__ adj,
                     const float* __restrict__ feat,
                     const float* __restrict__ W,
                     float* __restrict__ out)
{
    extern __shared__ char smem[];
    const uint32_t sb = smem_u32(smem);
    const int tid = threadIdx.x;
    const int lid = tid & 31;
    const int wid = tid >> 5;          // 0..3
    const int row0 = blockIdx.x * BM;

    float* sNT = reinterpret_cast<float*>(smem + OFF_SNT);
    float* sFT = reinterpret_cast<float*>(smem + OFF_SFT);
    float* sWT = reinterpret_cast<float*>(smem + OFF_SWT);

    // ---- stage W^T and feat block (regions disjoint from mainloop stages) ----
    for (int i = tid; i < COUT * 2 * CF; i += 128) {
        int o = i >> 7, c = i & 127;
        sWT[c * 64 + o] = W[i];
    }
    for (int j = tid; j < BM * (CF / 4); j += 128) {  // 1024 float4
        int r = j >> 4, q = j & 15;
        float4 v = __ldg(reinterpret_cast<const float4*>(feat + (size_t)(row0 + r) * CF + q * 4));
        sFT[(q * 4 + 0) * PITCH + r] = v.x;
        sFT[(q * 4 + 1) * PITCH + r] = v.y;
        sFT[(q * 4 + 2) * PITCH + r] = v.z;
        sFT[(q * 4 + 3) * PITCH + r] = v.w;
    }

    // ---- per-lane fragment offsets ----
    const int mrow = wid * 16;
    const int r8   = lid & 7;
    const int quad = lid >> 3;
    const uint32_t aoff  = (uint32_t)((mrow + r8 + (quad & 1) * 8) * A_STRIDE + (quad >> 1) * 16);
    const uint32_t boffB = (uint32_t)(((quad >> 1) * 8 + r8) * B_STRIDE + (quad & 1) * 16);
    const uint32_t boff8 = (uint32_t)((64 + r8) * B_STRIDE + ((lid >> 3) & 1) * 16);

    float acc[9][4];
    #pragma unroll
    for (int i = 0; i < 9; ++i)
        #pragma unroll
        for (int j = 0; j < 4; ++j) acc[i][j] = 0.0f;

    // ---- gmem load mapping ----
    const int arow = tid >> 1;                 // 0..63
    const int aseg = tid & 1;                  // 16-float half
    const size_t adjBase = (size_t)(row0 + arow) * CN + (size_t)aseg * 16;

    float4 ra[4];
    uint4  rb[3];

    auto LOAD = [&](int t) {
        const float* ap = adj + adjBase + (size_t)t * BK;
        ra[0] = __ldcs(reinterpret_cast<const float4*>(ap));
        ra[1] = __ldcs(reinterpret_cast<const float4*>(ap + 4));
        ra[2] = __ldcs(reinterpret_cast<const float4*>(ap + 8));
        ra[3] = __ldcs(reinterpret_cast<const float4*>(ap + 12));
        const uint4* bp = g_featB + t * 384 + tid;
        rb[0] = __ldg(bp);
        rb[1] = __ldg(bp + 128);
        rb[2] = __ldg(bp + 256);
    };

    auto STORE = [&](int buf) {
        char* sA = smem + buf * STAGE;
        char* sB = sA + A_BYTES;
        ULL* dst = reinterpret_cast<ULL*>(sA + arow * A_STRIDE + aseg * 32);
        #pragma unroll
        for (int i = 0; i < 4; ++i) {
            uint32_t lo = cvt2(ra[i].x, ra[i].y);
            uint32_t hi = cvt2(ra[i].z, ra[i].w);
            dst[i] = (ULL)lo | ((ULL)hi << 32);
        }
        #pragma unroll
        for (int i = 0; i < 3; ++i) {
            int j = tid + i * 128;
            int row = j >> 2, c = j & 3;
            *reinterpret_cast<uint4*>(sB + row * B_STRIDE + c * 16) = rb[i];
        }
    };

    auto COMPUTE = [&](int buf) {
        const uint32_t abase = sb + buf * STAGE + aoff;
        const uint32_t bbase = sb + buf * STAGE + A_BYTES;
        #pragma unroll
        for (int kc = 0; kc < 2; ++kc) {
            uint32_t a0, a1, a2, a3;
            LDSM4(a0, a1, a2, a3, abase + kc * 32);
            #pragma unroll
            for (int p = 0; p < 4; ++p) {
                uint32_t b0, b1, b2, b3;
                LDSM4(b0, b1, b2, b3, bbase + boffB + p * (16 * B_STRIDE) + kc * 32);
                mma16816(acc[2 * p],     a0, a1, a2, a3, b0, b1);
                mma16816(acc[2 * p + 1], a0, a1, a2, a3, b2, b3);
            }
            uint32_t c0, c1;
            LDSM2(c0, c1, bbase + boff8 + kc * 32);
            mma16816(acc[8], a0, a1, a2, a3, c0, c1);
        }
    };

    // ---- mainloop: register-prefetch double buffering, 1 barrier / tile ----
    LOAD(0);
    STORE(0);
    __syncthreads();

    #pragma unroll 1
    for (int t = 0; t < ITERS; ++t) {
        const int cur = t & 1;
        const bool hasNext = (t + 1) < ITERS;
        if (hasNext) LOAD(t + 1);
        COMPUTE(cur);
        if (hasNext) {
            STORE(cur ^ 1);
            __syncthreads();
        }
    }
    __syncthreads();   // all compute done before sNT overwrites stage region

    // ---- deg from ones-column (n-tile 8, col 64 => tig==0's c0/c2), broadcast in group ----
    {
        const int g = lid >> 2, tig = lid & 3;
        float degA = __shfl_sync(0xffffffffu, acc[8][0], lid & ~3);
        float degB = __shfl_sync(0xffffffffu, acc[8][2], lid & ~3);
        float inv0 = 1.0f / (degA + 1.0f);
        float inv1 = 1.0f / (degB + 1.0f);
        const int r0 = mrow + g, r1 = mrow + g + 8;
        #pragma unroll
        for (int nt = 0; nt < 8; ++nt) {
            const int c0 = nt * 8 + 2 * tig;
            sNT[c0 * PITCH + r0]       = acc[nt][0] * inv0;
            sNT[(c0 + 1) * PITCH + r0] = acc[nt][1] * inv0;
            sNT[c0 * PITCH + r1]       = acc[nt][2] * inv1;
            sNT[(c0 + 1) * PITCH + r1] = acc[nt][3] * inv1;
        }
    }
    __syncthreads();

    // ---- epilogue: out[r][o] = sum_c f[r][c]*W[o][c] + neigh[r][c]*W[o][64+c] (fp32) ----
    {
        const int o  = tid & 63;
        const int rg = tid >> 6;          // 0..1 -> rows rg*32..+31 (16 pairs)
        ULL acc_e[16];
        #pragma unroll
        for (int p = 0; p < 16; ++p) acc_e[p] = 0ull;

        #pragma unroll 2
        for (int c = 0; c < CF; ++c) {
            const float wa = sWT[c * 64 + o];
            const float wb = sWT[(c + 64) * 64 + o];
            const ULL wa2 = pack2(wa, wa);
            const ULL wb2 = pack2(wb, wb);
            const float* fb = sFT + c * PITCH + rg * 32;
            const float* nb = sNT + c * PITCH + rg * 32;
            #pragma unroll
            for (int p = 0; p < 16; ++p) {
                ULL f2 = *reinterpret_cast<const ULL*>(fb + 2 * p);
                ULL n2 = *reinterpret_cast<const ULL*>(nb + 2 * p);
                acc_e[p] = fma2(f2, wa2, acc_e[p]);
                acc_e[p] = fma2(n2, wb2, acc_e[p]);
            }
        }
        #pragma unroll
        for (int p = 0; p < 16; ++p) {
            float2 v = unpack2(acc_e[p]);
            const int r = row0 + rg * 32 + 2 * p;
            out[(size_t)r * COUT + o]       = v.x;
            out[(size_t)(r + 1) * COUT + o] = v.y;
        }
    }
}

// ---------------- host launch ----------------
extern "C" void kernel_launch(void* const* d_in, const int* in_sizes, int n_in,
                              void* d_out, int out_size)
{
    const float* adj  = nullptr;
    const float* feat = nullptr;
    const float* W    = nullptr;
    for (int i = 0; i < n_in; ++i) {
        const int s = in_sizes[i];
        if (s == CN * CN)            adj  = (const float*)d_in[i];
        else if (s == CN * CF)       feat = (const float*)d_in[i];
        else if (s == COUT * 2 * CF) W    = (const float*)d_in[i];
    }

    prep_featB<<<3072, 256>>>(feat);

    cudaFuncSetAttribute(sage_mma_kernel, cudaFuncAttributeMaxDynamicSharedMemorySize, SMEM_BYTES);
    sage_mma_kernel<<<CN / BM, 128, SMEM_BYTES>>>(adj, feat, W, (float*)d_out);
}

// round 9
// speedup vs baseline: 2.7183x; 1.9172x over previous
#include <cuda_runtime.h>
#include <cuda_bf16.h>
#include <cstdint>
#include <cstddef>

typedef unsigned long long ULL;

#define CN   8192
#define CF   64
#define COUT 64
#define BM   64
#define BK   32
#define ITERS 256          // CN / BK
#define STAGES 4

// f32 smem tiles, 144B row stride (128B data + 16B pad) -> conflict-free ldmatrix
#define A_ST 144
#define B_ST 144
#define B_ROWS 72                      // 64 feat + 1 ones + 7 pad
#define A_BYTES (BM * A_ST)            // 9216
#define B_BYTES (B_ROWS * B_ST)        // 10368
#define STAGE   (A_BYTES + B_BYTES)    // 19584

#define OFF_SFT (STAGES * STAGE)       // 78336
#define OFF_SWT (OFF_SFT + 16896)      // 95232
#define SMEM_BYTES (OFF_SWT + 32768)   // 128000
#define PITCH 66

// prep output: tf32-rounded feat^T blocked [t][96][32] f32, n=64 row is ones
__device__ float4 g_featB4[ITERS * 96 * 8];

// ---------------- helpers ----------------
__device__ __forceinline__ uint32_t smem_u32(const void* p) {
    uint32_t a;
    asm("{ .reg .u64 t; cvta.to.shared.u64 t, %1; cvt.u32.u64 %0, t; }" : "=r"(a) : "l"(p));
    return a;
}
__device__ __forceinline__ ULL fma2(ULL a, ULL b, ULL c) {
    ULL d; asm("fma.rn.f32x2 %0, %1, %2, %3;" : "=l"(d) : "l"(a), "l"(b), "l"(c)); return d;
}
__device__ __forceinline__ ULL pack2(float x, float y) {
    ULL u; asm("mov.b64 %0, {%1, %2};" : "=l"(u) : "f"(x), "f"(y)); return u;
}
__device__ __forceinline__ float2 unpack2(ULL u) {
    float2 f; asm("mov.b64 {%0, %1}, %2;" : "=f"(f.x), "=f"(f.y) : "l"(u)); return f;
}

#define CP_ASYNC16(smem_addr, gptr) \
    asm volatile("cp.async.cg.shared.global [%0], [%1], 16;" :: "r"(smem_addr), "l"(gptr))
#define CP_COMMIT() asm volatile("cp.async.commit_group;" ::: "memory")
#define CP_WAIT2()  asm volatile("cp.async.wait_group 2;" ::: "memory")

#define LDSM4(r0, r1, r2, r3, addr) \
    asm volatile("ldmatrix.sync.aligned.m8n8.x4.shared.b16 {%0,%1,%2,%3}, [%4];" \
                 : "=r"(r0), "=r"(r1), "=r"(r2), "=r"(r3) : "r"(addr))
#define LDSM2(r0, r1, addr) \
    asm volatile("ldmatrix.sync.aligned.m8n8.x2.shared.b16 {%0,%1}, [%2];" \
                 : "=r"(r0), "=r"(r1) : "r"(addr))

__device__ __forceinline__ void mma_tf32(float* d, uint32_t a0, uint32_t a1, uint32_t a2,
                                         uint32_t a3, uint32_t b0, uint32_t b1) {
    asm volatile("mma.sync.aligned.m16n8k8.row.col.f32.tf32.tf32.f32 "
                 "{%0,%1,%2,%3},{%4,%5,%6,%7},{%8,%9},{%0,%1,%2,%3};"
                 : "+f"(d[0]), "+f"(d[1]), "+f"(d[2]), "+f"(d[3])
                 : "r"(a0), "r"(a1), "r"(a2), "r"(a3), "r"(b0), "r"(b1));
}

// ---------------- prep: blocked tf32 feat^T with ones row ----------------
__global__ void prep_featB(const float* __restrict__ feat) {
    int idx = blockIdx.x * 256 + threadIdx.x;    // < 256*96*32 = 786432
    int t   = idx / 3072;
    int rem = idx - t * 3072;
    int n   = rem >> 5;
    int kk  = rem & 31;
    int k   = t * BK + kk;
    float v = (n < CF) ? feat[k * CF + n] : (n == CF ? 1.0f : 0.0f);
    uint32_t u;
    asm("cvt.rna.tf32.f32 %0, %1;" : "=r"(u) : "f"(v));
    reinterpret_cast<uint32_t*>(g_featB4)[idx] = u;
}

// ---------------- main fused kernel ----------------
__global__ __launch_bounds__(256, 1)
void sage_tf32_kernel(const float* __restrict__ adj,
                      const float* __restrict__ feat,
                      const float* __restrict__ W,
                      float* __restrict__ out)
{
    extern __shared__ char smem[];
    const uint32_t sb = smem_u32(smem);
    const int tid = threadIdx.x;
    const int lid = tid & 31;
    const int wid = tid >> 5;          // 0..7
    const int kg   = wid >> 2;         // k-group: 0 -> k 0-15, 1 -> k 16-31
    const int mwrp = wid & 3;
    const int mrow = mwrp * 16;
    const int row0 = blockIdx.x * BM;

    float* sNT = reinterpret_cast<float*>(smem);                // alias stage0 after loop
    float* sRD = reinterpret_cast<float*>(smem + STAGE);        // alias stage1 after loop
    float* sFT = reinterpret_cast<float*>(smem + OFF_SFT);
    float* sWT = reinterpret_cast<float*>(smem + OFF_SWT);

    // ---- stage W^T and feature block (regions disjoint from pipeline stages) ----
    for (int i = tid; i < COUT * 2 * CF; i += 256) {
        int o = i >> 7, c = i & 127;
        sWT[c * 64 + o] = W[i];
    }
    for (int j = tid; j < BM * (CF / 4); j += 256) {  // 1024 float4
        int r = j >> 4, q = j & 15;
        float4 v = __ldg(reinterpret_cast<const float4*>(feat + (size_t)(row0 + r) * CF + q * 4));
        sFT[(q * 4 + 0) * PITCH + r] = v.x;
        sFT[(q * 4 + 1) * PITCH + r] = v.y;
        sFT[(q * 4 + 2) * PITCH + r] = v.z;
        sFT[(q * 4 + 3) * PITCH + r] = v.w;
    }

    // ---- cp.async copy duties ----
    const int caRow = tid >> 3;        // A: rows 0..31 (i=0) / 32..63 (i=1)
    const int caSeg = tid & 7;
    const size_t adjBase = (size_t)(row0 + caRow) * CN + (size_t)caSeg * 4;

    auto COPY = [&](int buf, int t) {
        const uint32_t sA = sb + buf * STAGE;
        const uint32_t sB = sA + A_BYTES;
        // A: 64 rows x 8 chunks = 512; 2 per thread
        #pragma unroll
        for (int i = 0; i < 2; ++i) {
            const int row = caRow + i * 32;
            const float* g = adj + adjBase + (size_t)i * 32 * CN + (size_t)t * BK;
            CP_ASYNC16(sA + row * A_ST + caSeg * 16, g);
        }
        // B: 72 rows x 8 chunks = 576; 2-3 per thread
        const char* gb = reinterpret_cast<const char*>(g_featB4) + (size_t)t * (96 * 128);
        #pragma unroll
        for (int i = 0; i < 3; ++i) {
            const int j = tid + i * 256;
            if (j < 576) {
                const int n = j >> 3, seg = j & 7;
                CP_ASYNC16(sB + n * B_ST + seg * 16, gb + n * 128 + seg * 16);
            }
        }
    };

    // ---- ldmatrix lane offsets ----
    const uint32_t aoff = (uint32_t)((mrow + (lid & 7) + ((lid >> 3) & 1) * 8) * A_ST + (lid >> 4) * 16);
    const uint32_t boff = (uint32_t)((lid & 7) * B_ST + ((lid >> 3) & 1) * 16);

    float acc[9][4];
    #pragma unroll
    for (int i = 0; i < 9; ++i)
        #pragma unroll
        for (int j = 0; j < 4; ++j) acc[i][j] = 0.0f;

    auto COMPUTE = [&](int buf) {
        const uint32_t abase = sb + buf * STAGE + aoff;
        const uint32_t bbase = sb + buf * STAGE + A_BYTES + boff;
        #pragma unroll
        for (int kc = 0; kc < 2; ++kc) {
            const uint32_t kb = (uint32_t)((kg * 2 + kc) * 32);
            uint32_t a0, a1, a2, a3;
            LDSM4(a0, a1, a2, a3, abase + kb);
            #pragma unroll
            for (int p = 0; p < 9; ++p) {
                uint32_t b0, b1;
                LDSM2(b0, b1, bbase + (uint32_t)(p * 8 * B_ST) + kb);
                mma_tf32(acc[p], a0, a1, a2, a3, b0, b1);
            }
        }
    };

    // ---- pipeline: 4 stages, commit every iter, wait_group 2 ----
    COPY(0, 0); CP_COMMIT();
    COPY(1, 1); CP_COMMIT();
    COPY(2, 2); CP_COMMIT();

    #pragma unroll 1
    for (int t = 0; t < ITERS; ++t) {
        CP_WAIT2();
        __syncthreads();
        if (t + 3 < ITERS) COPY((t + 3) & 3, t + 3);
        CP_COMMIT();
        COMPUTE(t & 3);
    }
    __syncthreads();

    // ---- merge k-group partials via smem ----
    if (kg == 1) {
        float* dst = sRD + (size_t)(mwrp * 32 + lid) * 36;
        #pragma unroll
        for (int i = 0; i < 9; ++i)
            #pragma unroll
            for (int j = 0; j < 4; ++j) dst[i * 4 + j] = acc[i][j];
    }
    __syncthreads();

    if (kg == 0) {
        const float* src = sRD + (size_t)(mwrp * 32 + lid) * 36;
        #pragma unroll
        for (int i = 0; i < 9; ++i)
            #pragma unroll
            for (int j = 0; j < 4; ++j) acc[i][j] += src[i * 4 + j];

        // deg from ones-column (n-tile 8, col 64): c0/c2 of tig==0 lanes
        const int g = lid >> 2;
        float degA = __shfl_sync(0xffffffffu, acc[8][0], lid & ~3);
        float degB = __shfl_sync(0xffffffffu, acc[8][2], lid & ~3);
        float inv0 = 1.0f / (degA + 1.0f);
        float inv1 = 1.0f / (degB + 1.0f);
        const int tig = lid & 3;
        const int r0 = mrow + g, r1 = mrow + g + 8;
        #pragma unroll
        for (int nt = 0; nt < 8; ++nt) {
            const int c0 = nt * 8 + 2 * tig;
            sNT[c0 * PITCH + r0]       = acc[nt][0] * inv0;
            sNT[(c0 + 1) * PITCH + r0] = acc[nt][1] * inv0;
            sNT[c0 * PITCH + r1]       = acc[nt][2] * inv1;
            sNT[(c0 + 1) * PITCH + r1] = acc[nt][3] * inv1;
        }
    }
    __syncthreads();

    // ---- epilogue: out[r][o] = sum_c f[r][c]*W[o][c] + neigh[r][c]*W[o][64+c] (fp32) ----
    {
        const int o  = tid & 63;
        const int rg = tid >> 6;          // 0..3 -> rows rg*16..+15 (8 pairs)
        ULL acc_e[8];
        #pragma unroll
        for (int p = 0; p < 8; ++p) acc_e[p] = 0ull;

        #pragma unroll 4
        for (int c = 0; c < CF; ++c) {
            const float wa = sWT[c * 64 + o];
            const float wb = sWT[(c + 64) * 64 + o];
            const ULL wa2 = pack2(wa, wa);
            const ULL wb2 = pack2(wb, wb);
            const float* fb = sFT + c * PITCH + rg * 16;
            const float* nb = sNT + c * PITCH + rg * 16;
            #pragma unroll
            for (int p = 0; p < 8; ++p) {
                ULL f2 = *reinterpret_cast<const ULL*>(fb + 2 * p);
                ULL n2 = *reinterpret_cast<const ULL*>(nb + 2 * p);
                acc_e[p] = fma2(f2, wa2, acc_e[p]);
                acc_e[p] = fma2(n2, wb2, acc_e[p]);
            }
        }
        #pragma unroll
        for (int p = 0; p < 8; ++p) {
            float2 v = unpack2(acc_e[p]);
            const int r = row0 + rg * 16 + 2 * p;
            out[(size_t)r * COUT + o]       = v.x;
            out[(size_t)(r + 1) * COUT + o] = v.y;
        }
    }
}

// ---------------- host launch ----------------
extern "C" void kernel_launch(void* const* d_in, const int* in_sizes, int n_in,
                              void* d_out, int out_size)
{
    const float* adj  = nullptr;
    const float* feat = nullptr;
    const float* W    = nullptr;
    for (int i = 0; i < n_in; ++i) {
        const int s = in_sizes[i];
        if (s == CN * CN)            adj  = (const float*)d_in[i];
        else if (s == CN * CF)       feat = (const float*)d_in[i];
        else if (s == COUT * 2 * CF) W    = (const float*)d_in[i];
    }

    prep_featB<<<3072, 256>>>(feat);

    cudaFuncSetAttribute(sage_tf32_kernel, cudaFuncAttributeMaxDynamicSharedMemorySize, SMEM_BYTES);
    sage_tf32_kernel<<<CN / BM, 256, SMEM_BYTES>>>(adj, feat, W, (float*)d_out);
}

// round 10
// speedup vs baseline: 2.7950x; 1.0282x over previous
#include <cuda_runtime.h>
#include <cuda_bf16.h>
#include <cstdint>
#include <cstddef>

typedef unsigned long long ULL;

#define CN   8192
#define CF   64
#define COUT 64
#define BM   32
#define BK   32
#define ITERS 256          // CN / BK
#define STAGES 4

// f32 smem tiles, 144B row stride (128B data + 16B pad) -> conflict-free ldmatrix
#define A_ST 144
#define B_ST 144
#define B_ROWS 72                      // 64 feat + 1 ones + 7 pad
#define A_BYTES (BM * A_ST)            // 4608
#define B_BYTES (B_ROWS * B_ST)        // 10368
#define STAGE   (A_BYTES + B_BYTES)    // 14976

#define OFF_SFT (STAGES * STAGE)       // 59904
#define OFF_SWT (OFF_SFT + 8704)       // 68608
#define SMEM_BYTES (OFF_SWT + 32768)   // 101376  -> 2 CTAs/SM
#define PITCH 34

// prep output: tf32-rounded feat^T blocked [t][96][32] f32, n=64 row is ones
__device__ float4 g_featB4[ITERS * 96 * 8];

// ---------------- helpers ----------------
__device__ __forceinline__ uint32_t smem_u32(const void* p) {
    uint32_t a;
    asm("{ .reg .u64 t; cvta.to.shared.u64 t, %1; cvt.u32.u64 %0, t; }" : "=r"(a) : "l"(p));
    return a;
}
__device__ __forceinline__ ULL fma2(ULL a, ULL b, ULL c) {
    ULL d; asm("fma.rn.f32x2 %0, %1, %2, %3;" : "=l"(d) : "l"(a), "l"(b), "l"(c)); return d;
}
__device__ __forceinline__ ULL pack2(float x, float y) {
    ULL u; asm("mov.b64 %0, {%1, %2};" : "=l"(u) : "f"(x), "f"(y)); return u;
}
__device__ __forceinline__ float2 unpack2(ULL u) {
    float2 f; asm("mov.b64 {%0, %1}, %2;" : "=f"(f.x), "=f"(f.y) : "l"(u)); return f;
}

#define CP_ASYNC16(smem_addr, gptr) \
    asm volatile("cp.async.cg.shared.global [%0], [%1], 16;" :: "r"(smem_addr), "l"(gptr))
#define CP_COMMIT() asm volatile("cp.async.commit_group;" ::: "memory")
#define CP_WAIT2()  asm volatile("cp.async.wait_group 2;" ::: "memory")

#define LDSM4(r0, r1, r2, r3, addr) \
    asm volatile("ldmatrix.sync.aligned.m8n8.x4.shared.b16 {%0,%1,%2,%3}, [%4];" \
                 : "=r"(r0), "=r"(r1), "=r"(r2), "=r"(r3) : "r"(addr))
#define LDSM2(r0, r1, addr) \
    asm volatile("ldmatrix.sync.aligned.m8n8.x2.shared.b16 {%0,%1}, [%2];" \
                 : "=r"(r0), "=r"(r1) : "r"(addr))

__device__ __forceinline__ void mma_tf32(float* d, uint32_t a0, uint32_t a1, uint32_t a2,
                                         uint32_t a3, uint32_t b0, uint32_t b1) {
    asm volatile("mma.sync.aligned.m16n8k8.row.col.f32.tf32.tf32.f32 "
                 "{%0,%1,%2,%3},{%4,%5,%6,%7},{%8,%9},{%0,%1,%2,%3};"
                 : "+f"(d[0]), "+f"(d[1]), "+f"(d[2]), "+f"(d[3])
                 : "r"(a0), "r"(a1), "r"(a2), "r"(a3), "r"(b0), "r"(b1));
}

// ---------------- prep: blocked tf32 feat^T with ones row ----------------
__global__ void prep_featB(const float* __restrict__ feat) {
    int idx = blockIdx.x * 256 + threadIdx.x;    // < 256*96*32 = 786432
    int t   = idx / 3072;
    int rem = idx - t * 3072;
    int n   = rem >> 5;
    int kk  = rem & 31;
    int k   = t * BK + kk;
    float v = (n < CF) ? feat[k * CF + n] : (n == CF ? 1.0f : 0.0f);
    uint32_t u;
    asm("cvt.rna.tf32.f32 %0, %1;" : "=r"(u) : "f"(v));
    reinterpret_cast<uint32_t*>(g_featB4)[idx] = u;
}

// ---------------- main fused kernel ----------------
__global__ __launch_bounds__(256, 2)
void sage_tf32_kernel(const float* __restrict__ adj,
                      const float* __restrict__ feat,
                      const float* __restrict__ W,
                      float* __restrict__ out)
{
    extern __shared__ char smem[];
    const uint32_t sb = smem_u32(smem);
    const int tid = threadIdx.x;
    const int lid = tid & 31;
    const int wid = tid >> 5;          // 0..7
    const int mw  = wid & 1;           // m-tile: rows mw*16..+15
    const int kg  = wid >> 1;          // k-group: k-chunk of 8 within BK=32
    const int mrow = mw * 16;
    const int row0 = blockIdx.x * BM;

    float* sNT = reinterpret_cast<float*>(smem);                // alias stage0 after loop
    float* sRD = reinterpret_cast<float*>(smem + STAGE);        // alias stages1-2 after loop
    float* sFT = reinterpret_cast<float*>(smem + OFF_SFT);
    float* sWT = reinterpret_cast<float*>(smem + OFF_SWT);

    // ---- stage W^T and feature block (regions disjoint from pipeline stages) ----
    for (int i = tid; i < COUT * 2 * CF; i += 256) {
        int o = i >> 7, c = i & 127;
        sWT[c * 64 + o] = W[i];
    }
    for (int j = tid; j < BM * (CF / 4); j += 256) {  // 512 float4
        int r = j >> 4, q = j & 15;
        float4 v = __ldg(reinterpret_cast<const float4*>(feat + (size_t)(row0 + r) * CF + q * 4));
        sFT[(q * 4 + 0) * PITCH + r] = v.x;
        sFT[(q * 4 + 1) * PITCH + r] = v.y;
        sFT[(q * 4 + 2) * PITCH + r] = v.z;
        sFT[(q * 4 + 3) * PITCH + r] = v.w;
    }

    // ---- cp.async copy duties ----
    const int caRow = tid >> 3;        // A: 32 rows x 8 chunks = 256 -> 1/thread
    const int caSeg = tid & 7;
    const size_t adjBase = (size_t)(row0 + caRow) * CN + (size_t)caSeg * 4;

    auto COPY = [&](int buf, int t) {
        const uint32_t sA = sb + buf * STAGE;
        const uint32_t sB = sA + A_BYTES;
        CP_ASYNC16(sA + caRow * A_ST + caSeg * 16, adj + adjBase + (size_t)t * BK);
        // B: 72 rows x 8 chunks = 576; up to 3 per thread
        const char* gb = reinterpret_cast<const char*>(g_featB4) + (size_t)t * (96 * 128);
        #pragma unroll
        for (int i = 0; i < 3; ++i) {
            const int j = tid + i * 256;
            if (j < 576) {
                const int n = j >> 3, seg = j & 7;
                CP_ASYNC16(sB + n * B_ST + seg * 16, gb + n * 128 + seg * 16);
            }
        }
    };

    // ---- ldmatrix lane offsets ----
    const uint32_t aoff = (uint32_t)((mrow + (lid & 7) + ((lid >> 3) & 1) * 8) * A_ST + (lid >> 4) * 16);
    const uint32_t boff = (uint32_t)((lid & 7) * B_ST + ((lid >> 3) & 1) * 16);
    const uint32_t kb   = (uint32_t)(kg * 32);     // 8 f32 = 32B per k-chunk

    float acc[9][4];
    #pragma unroll
    for (int i = 0; i < 9; ++i)
        #pragma unroll
        for (int j = 0; j < 4; ++j) acc[i][j] = 0.0f;

    auto COMPUTE = [&](int buf) {
        const uint32_t abase = sb + buf * STAGE + aoff + kb;
        const uint32_t bbase = sb + buf * STAGE + A_BYTES + boff + kb;
        uint32_t a0, a1, a2, a3;
        LDSM4(a0, a1, a2, a3, abase);
        #pragma unroll
        for (int p = 0; p < 9; ++p) {
            uint32_t b0, b1;
            LDSM2(b0, b1, bbase + (uint32_t)(p * 8 * B_ST));
            mma_tf32(acc[p], a0, a1, a2, a3, b0, b1);
        }
    };

    // ---- pipeline: 4 stages, commit every iter, wait_group 2 ----
    COPY(0, 0); CP_COMMIT();
    COPY(1, 1); CP_COMMIT();
    COPY(2, 2); CP_COMMIT();

    #pragma unroll 1
    for (int t = 0; t < ITERS; ++t) {
        CP_WAIT2();
        __syncthreads();
        if (t + 3 < ITERS) COPY((t + 3) & 3, t + 3);
        CP_COMMIT();
        COMPUTE(t & 3);
    }
    __syncthreads();

    // ---- merge 4 k-group partials via smem ----
    if (kg != 0) {
        float* dst = sRD + (size_t)(((kg - 1) * 2 + mw) * 32 + lid) * 36;
        #pragma unroll
        for (int i = 0; i < 9; ++i)
            #pragma unroll
            for (int j = 0; j < 4; ++j) dst[i * 4 + j] = acc[i][j];
    }
    __syncthreads();

    if (kg == 0) {
        #pragma unroll
        for (int q = 0; q < 3; ++q) {
            const float* src = sRD + (size_t)((q * 2 + mw) * 32 + lid) * 36;
            #pragma unroll
            for (int i = 0; i < 9; ++i)
                #pragma unroll
                for (int j = 0; j < 4; ++j) acc[i][j] += src[i * 4 + j];
        }

        // deg from ones-column (n-tile 8, col 64): c0/c2 of tig==0 lanes
        const int g = lid >> 2;
        float degA = __shfl_sync(0xffffffffu, acc[8][0], lid & ~3);
        float degB = __shfl_sync(0xffffffffu, acc[8][2], lid & ~3);
        float inv0 = 1.0f / (degA + 1.0f);
        float inv1 = 1.0f / (degB + 1.0f);
        const int tig = lid & 3;
        const int r0 = mrow + g, r1 = mrow + g + 8;
        #pragma unroll
        for (int nt = 0; nt < 8; ++nt) {
            const int c0 = nt * 8 + 2 * tig;
            sNT[c0 * PITCH + r0]       = acc[nt][0] * inv0;
            sNT[(c0 + 1) * PITCH + r0] = acc[nt][1] * inv0;
            sNT[c0 * PITCH + r1]       = acc[nt][2] * inv1;
            sNT[(c0 + 1) * PITCH + r1] = acc[nt][3] * inv1;
        }
    }
    __syncthreads();

    // ---- epilogue: out[r][o] = sum_c f[r][c]*W[o][c] + neigh[r][c]*W[o][64+c] (fp32) ----
    {
        const int o  = tid & 63;
        const int rg = tid >> 6;          // 0..3 -> rows rg*8..+7 (4 pairs)
        ULL acc_e[4];
        #pragma unroll
        for (int p = 0; p < 4; ++p) acc_e[p] = 0ull;

        #pragma unroll 4
        for (int c = 0; c < CF; ++c) {
            const float wa = sWT[c * 64 + o];
            const float wb = sWT[(c + 64) * 64 + o];
            const ULL wa2 = pack2(wa, wa);
            const ULL wb2 = pack2(wb, wb);
            const float* fb = sFT + c * PITCH + rg * 8;
            const float* nb = sNT + c * PITCH + rg * 8;
            #pragma unroll
            for (int p = 0; p < 4; ++p) {
                ULL f2 = *reinterpret_cast<const ULL*>(fb + 2 * p);
                ULL n2 = *reinterpret_cast<const ULL*>(nb + 2 * p);
                acc_e[p] = fma2(f2, wa2, acc_e[p]);
                acc_e[p] = fma2(n2, wb2, acc_e[p]);
            }
        }
        #pragma unroll
        for (int p = 0; p < 4; ++p) {
            float2 v = unpack2(acc_e[p]);
            const int r = row0 + rg * 8 + 2 * p;
            out[(size_t)r * COUT + o]       = v.x;
            out[(size_t)(r + 1) * COUT + o] = v.y;
        }
    }
}

// ---------------- host launch ----------------
extern "C" void kernel_launch(void* const* d_in, const int* in_sizes, int n_in,
                              void* d_out, int out_size)
{
    const float* adj  = nullptr;
    const float* feat = nullptr;
    const float* W    = nullptr;
    for (int i = 0; i < n_in; ++i) {
        const int s = in_sizes[i];
        if (s == CN * CN)            adj  = (const float*)d_in[i];
        else if (s == CN * CF)       feat = (const float*)d_in[i];
        else if (s == COUT * 2 * CF) W    = (const float*)d_in[i];
    }

    prep_featB<<<3072, 256>>>(feat);

    cudaFuncSetAttribute(sage_tf32_kernel, cudaFuncAttributeMaxDynamicSharedMemorySize, SMEM_BYTES);
    sage_tf32_kernel<<<CN / BM, 256, SMEM_BYTES>>>(adj, feat, W, (float*)d_out);
}